// round 1
// baseline (speedup 1.0000x reference)
#include <cuda_runtime.h>
#include <cuda_bf16.h>

#define BDIM 4
#define TDIM 2048
#define CDIM 768
#define HDIM 12
#define DDIM 64
#define C3   2304
#define MROWS (BDIM * TDIM)

// Scratch (device globals: allocation-free rule)
__device__ float g_qkv[MROWS * C3];   // 75.5 MB: [m][0:768]=Q, [768:1536]=K, [1536:2304]=V
__device__ float g_y[MROWS * CDIM];   // 25 MB attention output

// ---------------------------------------------------------------------------
// Generic tiled fp32 GEMM: out[M,N] = A[M,K] @ W[K,N] + bias[N]
// BM=BN=64, BK=16, 256 threads, 4x4 microtile per thread. Assumes divisibility.
// ---------------------------------------------------------------------------
__global__ void gemm_bias(const float* __restrict__ A, const float* __restrict__ W,
                          const float* __restrict__ bias, float* __restrict__ out,
                          int M, int N, int K)
{
    __shared__ float As[16][64];   // [k][m]
    __shared__ float Bs[16][64];   // [k][n]
    const int tid = threadIdx.x;
    const int tx = tid & 15, ty = tid >> 4;
    const int m0 = blockIdx.y * 64;
    const int n0 = blockIdx.x * 64;

    float acc[4][4] = {};

    for (int k0 = 0; k0 < K; k0 += 16) {
        // A tile 64x16 -> transposed into As[k][m]
        {
            int row = tid >> 2;            // 0..63
            int kq  = (tid & 3) << 2;      // 0,4,8,12
            float4 v = *(const float4*)(A + (size_t)(m0 + row) * K + k0 + kq);
            As[kq + 0][row] = v.x;
            As[kq + 1][row] = v.y;
            As[kq + 2][row] = v.z;
            As[kq + 3][row] = v.w;
        }
        // B tile 16x64 straight
        {
            int krow = tid >> 4;           // 0..15
            int nq   = (tid & 15) << 2;    // 0..60
            *(float4*)&Bs[krow][nq] =
                *(const float4*)(W + (size_t)(k0 + krow) * N + n0 + nq);
        }
        __syncthreads();

        #pragma unroll
        for (int kk = 0; kk < 16; kk++) {
            float4 a4 = *(const float4*)&As[kk][ty << 2];
            float4 b4 = *(const float4*)&Bs[kk][tx << 2];
            float a[4] = {a4.x, a4.y, a4.z, a4.w};
            float b[4] = {b4.x, b4.y, b4.z, b4.w};
            #pragma unroll
            for (int i = 0; i < 4; i++)
                #pragma unroll
                for (int j = 0; j < 4; j++)
                    acc[i][j] += a[i] * b[j];
        }
        __syncthreads();
    }

    float4 bb = *(const float4*)(bias + n0 + (tx << 2));
    #pragma unroll
    for (int i = 0; i < 4; i++) {
        float4 o;
        o.x = acc[i][0] + bb.x;
        o.y = acc[i][1] + bb.y;
        o.z = acc[i][2] + bb.z;
        o.w = acc[i][3] + bb.w;
        *(float4*)(out + (size_t)(m0 + (ty << 2) + i) * N + n0 + (tx << 2)) = o;
    }
}

// ---------------------------------------------------------------------------
// Flash attention, fp32, causal. One block per (q-tile 64, head, batch).
// Smem: Qt[d][r], Kt[d][c], Vs[c][d], Pt[c][r], all 64x68 padded (69632 B).
// ---------------------------------------------------------------------------
#define SPAD 68

extern __shared__ float fa_smem[];

__global__ void flash_attn(const float* __restrict__ qkv, float* __restrict__ y)
{
    float* Qt = fa_smem;                // [64][SPAD]  (d-major: Qt[d*SPAD + r])
    float* Kt = Qt + 64 * SPAD;         // [64][SPAD]  (d-major: Kt[d*SPAD + c])
    float* Vs = Kt + 64 * SPAD;         // [64][SPAD]  (c-major: Vs[c*SPAD + d])
    float* Pt = Vs + 64 * SPAD;         // [64][SPAD]  (c-major: Pt[c*SPAD + r])

    const int tid = threadIdx.x;
    const int tx = tid & 15, ty = tid >> 4;
    const int itile = blockIdx.x;
    const int h = blockIdx.y;
    const int b = blockIdx.z;
    const int q0 = itile * 64;
    const size_t base = (size_t)b * TDIM * C3;
    const float scale = 0.125f;   // 1/sqrt(64)

    // Load Q tile transposed: Qt[d][r]
    for (int idx = tid; idx < 64 * 16; idx += 256) {
        int r  = idx >> 4;
        int dq = (idx & 15) << 2;
        float4 v = *(const float4*)(qkv + base + (size_t)(q0 + r) * C3 + h * DDIM + dq);
        Qt[(dq + 0) * SPAD + r] = v.x;
        Qt[(dq + 1) * SPAD + r] = v.y;
        Qt[(dq + 2) * SPAD + r] = v.z;
        Qt[(dq + 3) * SPAD + r] = v.w;
    }

    float mrow[4], lrow[4], acc[4][4];
    #pragma unroll
    for (int i = 0; i < 4; i++) {
        mrow[i] = -1e30f;
        lrow[i] = 0.f;
        #pragma unroll
        for (int j = 0; j < 4; j++) acc[i][j] = 0.f;
    }

    for (int jt = 0; jt <= itile; jt++) {
        const int k0 = jt * 64;
        __syncthreads();   // previous iter's smem consumers done (also covers Q load)

        // Load K tile transposed (Kt[d][c]) and V tile straight (Vs[c][d])
        for (int idx = tid; idx < 64 * 16; idx += 256) {
            int c  = idx >> 4;
            int dq = (idx & 15) << 2;
            const float* kp = qkv + base + (size_t)(k0 + c) * C3 + CDIM + h * DDIM + dq;
            float4 kv = *(const float4*)kp;
            Kt[(dq + 0) * SPAD + c] = kv.x;
            Kt[(dq + 1) * SPAD + c] = kv.y;
            Kt[(dq + 2) * SPAD + c] = kv.z;
            Kt[(dq + 3) * SPAD + c] = kv.w;
            float4 vv = *(const float4*)(kp + CDIM);   // V is +768 after K
            *(float4*)&Vs[c * SPAD + dq] = vv;
        }
        __syncthreads();

        // S = Q @ K^T  (4x4 microtile, inner product over d)
        float s[4][4] = {};
        #pragma unroll 8
        for (int d = 0; d < DDIM; d++) {
            float4 a4 = *(const float4*)&Qt[d * SPAD + (ty << 2)];
            float4 b4 = *(const float4*)&Kt[d * SPAD + (tx << 2)];
            float a[4] = {a4.x, a4.y, a4.z, a4.w};
            float bb[4] = {b4.x, b4.y, b4.z, b4.w};
            #pragma unroll
            for (int i = 0; i < 4; i++)
                #pragma unroll
                for (int j = 0; j < 4; j++)
                    s[i][j] += a[i] * bb[j];
        }

        // Scale + causal mask (diagonal tile only)
        const bool diag = (jt == itile);
        #pragma unroll
        for (int i = 0; i < 4; i++) {
            int rg = q0 + (ty << 2) + i;
            #pragma unroll
            for (int jj = 0; jj < 4; jj++) {
                float sv = s[i][jj] * scale;
                if (diag) {
                    int cg = k0 + (tx << 2) + jj;
                    if (cg > rg) sv = -1e30f;
                }
                s[i][jj] = sv;
            }
        }

        // Online softmax: rows owned by 16 lanes sharing ty (lane groups of 16)
        #pragma unroll
        for (int i = 0; i < 4; i++) {
            float mx = fmaxf(fmaxf(s[i][0], s[i][1]), fmaxf(s[i][2], s[i][3]));
            #pragma unroll
            for (int off = 8; off >= 1; off >>= 1)
                mx = fmaxf(mx, __shfl_xor_sync(0xffffffffu, mx, off));
            float mn = fmaxf(mrow[i], mx);
            float alpha = __expf(mrow[i] - mn);
            mrow[i] = mn;
            float rs = 0.f;
            #pragma unroll
            for (int jj = 0; jj < 4; jj++) {
                float p = __expf(s[i][jj] - mn);
                s[i][jj] = p;
                rs += p;
            }
            #pragma unroll
            for (int off = 8; off >= 1; off >>= 1)
                rs += __shfl_xor_sync(0xffffffffu, rs, off);
            lrow[i] = lrow[i] * alpha + rs;
            #pragma unroll
            for (int jj = 0; jj < 4; jj++) acc[i][jj] *= alpha;
        }

        // Stage P transposed: Pt[c][r]
        #pragma unroll
        for (int i = 0; i < 4; i++)
            #pragma unroll
            for (int jj = 0; jj < 4; jj++)
                Pt[((tx << 2) + jj) * SPAD + (ty << 2) + i] = s[i][jj];
        __syncthreads();

        // O += P @ V
        #pragma unroll 8
        for (int c = 0; c < 64; c++) {
            float4 a4 = *(const float4*)&Pt[c * SPAD + (ty << 2)];
            float4 b4 = *(const float4*)&Vs[c * SPAD + (tx << 2)];
            float a[4] = {a4.x, a4.y, a4.z, a4.w};
            float bb[4] = {b4.x, b4.y, b4.z, b4.w};
            #pragma unroll
            for (int i = 0; i < 4; i++)
                #pragma unroll
                for (int j = 0; j < 4; j++)
                    acc[i][j] += a[i] * bb[j];
        }
    }

    // Epilogue: normalize and write y[b][t][h*64+d]
    #pragma unroll
    for (int i = 0; i < 4; i++) {
        float inv = 1.f / lrow[i];
        float4 o;
        o.x = acc[i][0] * inv;
        o.y = acc[i][1] * inv;
        o.z = acc[i][2] * inv;
        o.w = acc[i][3] * inv;
        *(float4*)(y + ((size_t)b * TDIM + q0 + (ty << 2) + i) * CDIM
                     + h * DDIM + (tx << 2)) = o;
    }
}

// ---------------------------------------------------------------------------
extern "C" void kernel_launch(void* const* d_in, const int* in_sizes, int n_in,
                              void* d_out, int out_size)
{
    const float* x     = (const float*)d_in[0];
    const float* Wqkv  = (const float*)d_in[1];
    const float* bqkv  = (const float*)d_in[2];
    const float* Wproj = (const float*)d_in[3];
    const float* bproj = (const float*)d_in[4];
    float* out = (float*)d_out;

    float* qkv; cudaGetSymbolAddress((void**)&qkv, g_qkv);
    float* yb;  cudaGetSymbolAddress((void**)&yb, g_y);

    // 1) QKV projection: [8192,768] @ [768,2304] + b
    gemm_bias<<<dim3(C3 / 64, MROWS / 64), 256>>>(x, Wqkv, bqkv, qkv, MROWS, C3, CDIM);

    // 2) Causal flash attention per (q-tile, head, batch)
    size_t smem = (size_t)4 * 64 * SPAD * sizeof(float);   // 69632 B
    cudaFuncSetAttribute(flash_attn, cudaFuncAttributeMaxDynamicSharedMemorySize, (int)smem);
    flash_attn<<<dim3(TDIM / 64, HDIM, BDIM), 256, smem>>>(qkv, yb);

    // 3) Output projection: [8192,768] @ [768,768] + b
    gemm_bias<<<dim3(CDIM / 64, MROWS / 64), 256>>>(yb, Wproj, bproj, out, MROWS, CDIM, CDIM);
}

// round 2
// speedup vs baseline: 2.5616x; 2.5616x over previous
#include <cuda_runtime.h>
#include <cuda_bf16.h>
#include <cstdint>

#define BDIM 4
#define TDIM 2048
#define CDIM 768
#define HDIM 12
#define DDIM 64
#define C3   2304
#define MROWS (BDIM * TDIM)

// Scratch (device globals: allocation-free rule)
__device__ float g_qkv[MROWS * C3];   // [m][0:768]=Q, [768:1536]=K, [1536:2304]=V
__device__ float g_y[MROWS * CDIM];   // attention output

// ---------------------------------------------------------------------------
// tf32 helpers
// ---------------------------------------------------------------------------
__device__ __forceinline__ unsigned f2tf(float x) {
    unsigned u;
    asm("cvt.rna.tf32.f32 %0, %1;" : "=r"(u) : "f"(x));
    return u;
}

__device__ __forceinline__ void mma16n8k8(float d[4], const unsigned a[4], const unsigned b[2]) {
    asm volatile(
        "mma.sync.aligned.m16n8k8.row.col.f32.tf32.tf32.f32 "
        "{%0,%1,%2,%3}, {%4,%5,%6,%7}, {%8,%9}, {%0,%1,%2,%3};\n"
        : "+f"(d[0]), "+f"(d[1]), "+f"(d[2]), "+f"(d[3])
        : "r"(a[0]), "r"(a[1]), "r"(a[2]), "r"(a[3]), "r"(b[0]), "r"(b[1]));
}

// ---------------------------------------------------------------------------
// tf32 GEMM: out[M,N] = A[M,K] @ W[K,N] + bias.  Block 128x128, BK=16,
// 256 threads = 8 warps of 64x32 warp tiles.  M%128==0, N%128==0, K%16==0.
// As[m][k] stride 20 (==4 mod 32: conflict-free A-frag LDS)
// Bs[k][n] stride 136 (==8 mod 32: conflict-free B-frag LDS)
// ---------------------------------------------------------------------------
__global__ __launch_bounds__(256, 2)
void gemm_tf32(const float* __restrict__ A, const float* __restrict__ W,
               const float* __restrict__ bias, float* __restrict__ out,
               int M, int N, int K)
{
    __shared__ unsigned As[128 * 20];
    __shared__ unsigned Bs[16 * 136];

    const int tid  = threadIdx.x;
    const int lane = tid & 31, wid = tid >> 5;
    const int g = lane >> 2, t = lane & 3;
    const int wm = (wid & 1) * 64;     // warp m-offset in block
    const int wn = (wid >> 1) * 32;    // warp n-offset in block
    const int m0 = blockIdx.y * 128, n0 = blockIdx.x * 128;

    // staging mapping
    const int am = tid >> 1, ak = (tid & 1) * 8;   // A: row am, k cols ak..ak+7
    const int bn = tid & 127, bk0 = (tid >> 7) * 8; // B: col n0+bn, k rows bk0..bk0+7

    const float* Ap = A + (size_t)(m0 + am) * K + ak;
    const float* Wp = W + (size_t)bk0 * N + n0 + bn;

    float acc[4][4][4] = {};

    float4 pa0 = *(const float4*)(Ap);
    float4 pa1 = *(const float4*)(Ap + 4);
    float pb[8];
    #pragma unroll
    for (int j = 0; j < 8; j++) pb[j] = Wp[(size_t)j * N];

    for (int k0 = 0; k0 < K; k0 += 16) {
        // store staged tile (fp32 -> tf32)
        {
            unsigned* as = &As[am * 20 + ak];
            as[0] = f2tf(pa0.x); as[1] = f2tf(pa0.y); as[2] = f2tf(pa0.z); as[3] = f2tf(pa0.w);
            as[4] = f2tf(pa1.x); as[5] = f2tf(pa1.y); as[6] = f2tf(pa1.z); as[7] = f2tf(pa1.w);
            #pragma unroll
            for (int j = 0; j < 8; j++) Bs[(bk0 + j) * 136 + bn] = f2tf(pb[j]);
        }
        __syncthreads();

        // prefetch next tile
        if (k0 + 16 < K) {
            pa0 = *(const float4*)(Ap + k0 + 16);
            pa1 = *(const float4*)(Ap + k0 + 20);
            const float* wp = Wp + (size_t)(k0 + 16) * N;
            #pragma unroll
            for (int j = 0; j < 8; j++) pb[j] = wp[(size_t)j * N];
        }

        #pragma unroll
        for (int kk = 0; kk < 16; kk += 8) {
            unsigned af[4][4], bf[4][2];
            #pragma unroll
            for (int mi = 0; mi < 4; mi++) {
                int r = wm + mi * 16;
                af[mi][0] = As[(r + g) * 20 + kk + t];
                af[mi][1] = As[(r + g + 8) * 20 + kk + t];
                af[mi][2] = As[(r + g) * 20 + kk + t + 4];
                af[mi][3] = As[(r + g + 8) * 20 + kk + t + 4];
            }
            #pragma unroll
            for (int ni = 0; ni < 4; ni++) {
                int c = wn + ni * 8;
                bf[ni][0] = Bs[(kk + t) * 136 + c + g];
                bf[ni][1] = Bs[(kk + t + 4) * 136 + c + g];
            }
            #pragma unroll
            for (int mi = 0; mi < 4; mi++)
                #pragma unroll
                for (int ni = 0; ni < 4; ni++)
                    mma16n8k8(acc[mi][ni], af[mi], bf[ni]);
        }
        __syncthreads();
    }

    // epilogue: bias + store (float2 per c-frag row pair)
    #pragma unroll
    for (int mi = 0; mi < 4; mi++) {
        #pragma unroll
        for (int ni = 0; ni < 4; ni++) {
            int r = m0 + wm + mi * 16 + g;
            int c = n0 + wn + ni * 8 + 2 * t;
            float b0 = bias[c], b1 = bias[c + 1];
            *(float2*)(out + (size_t)r * N + c) =
                make_float2(acc[mi][ni][0] + b0, acc[mi][ni][1] + b1);
            *(float2*)(out + (size_t)(r + 8) * N + c) =
                make_float2(acc[mi][ni][2] + b0, acc[mi][ni][3] + b1);
        }
    }
}

// ---------------------------------------------------------------------------
// tf32 flash attention, causal.  Block = 128 q-rows x (head,batch).
// 256 threads = 8 warps, each warp owns 16 q-rows.
// Qs[r][d] stride 68, Ks[d][c] stride 72, Vs[c][d] stride 72, Ps[r][c] stride 68.
// ---------------------------------------------------------------------------
#define QST 68
#define KST 72

__global__ __launch_bounds__(256, 2)
void flash_tf32(const float* __restrict__ qkv, float* __restrict__ y)
{
    extern __shared__ unsigned sm[];
    unsigned* Qs = sm;                  // [128][QST]
    unsigned* Ks = Qs + 128 * QST;      // [64][KST]  d-major (K^T)
    unsigned* Vs = Ks + 64 * KST;       // [64][KST]  c-major
    unsigned* Ps = Vs + 64 * KST;       // [128][QST]

    const int tid  = threadIdx.x;
    const int lane = tid & 31, wid = tid >> 5;
    const int g = lane >> 2, t = lane & 3;
    const int r0 = wid * 16;            // warp's q-row offset in block
    const int itile = blockIdx.x, h = blockIdx.y, b = blockIdx.z;
    const int q0 = itile * 128;
    const size_t base = (size_t)b * TDIM * C3;
    const float scale = 0.125f;         // 1/sqrt(64)

    // stage Q (tf32)
    for (int idx = tid; idx < 128 * 16; idx += 256) {
        int r = idx >> 4, dq = (idx & 15) << 2;
        float4 v = *(const float4*)(qkv + base + (size_t)(q0 + r) * C3 + h * DDIM + dq);
        unsigned* qp = &Qs[r * QST + dq];
        qp[0] = f2tf(v.x); qp[1] = f2tf(v.y); qp[2] = f2tf(v.z); qp[3] = f2tf(v.w);
    }

    float O[8][4] = {};
    float mrow[2] = {-1e30f, -1e30f};
    float lrow[2] = {0.f, 0.f};

    const int nkt = (q0 + 128) >> 6;    // 64-key tiles needed
    for (int jt = 0; jt < nkt; jt++) {
        const int k0 = jt * 64;
        __syncthreads();   // prior iter consumers done with Ks/Vs; (iter 0: Q stores)

        // stage K transposed: Ks[d][c]
        for (int idx = tid; idx < 1024; idx += 256) {
            int c = idx & 63, dq = (idx >> 6) << 2;
            float4 kv = *(const float4*)(qkv + base + (size_t)(k0 + c) * C3 + CDIM + h * DDIM + dq);
            Ks[(dq + 0) * KST + c] = f2tf(kv.x);
            Ks[(dq + 1) * KST + c] = f2tf(kv.y);
            Ks[(dq + 2) * KST + c] = f2tf(kv.z);
            Ks[(dq + 3) * KST + c] = f2tf(kv.w);
        }
        // stage V: Vs[c][d]
        for (int idx = tid; idx < 1024; idx += 256) {
            int c = idx >> 4, dq = (idx & 15) << 2;
            float4 vv = *(const float4*)(qkv + base + (size_t)(k0 + c) * C3 + 2 * CDIM + h * DDIM + dq);
            unsigned* vp = &Vs[c * KST + dq];
            vp[0] = f2tf(vv.x); vp[1] = f2tf(vv.y); vp[2] = f2tf(vv.z); vp[3] = f2tf(vv.w);
        }
        __syncthreads();

        const bool active = (k0 <= q0 + r0 + 15);   // warp-uniform
        if (active) {
            // S = Q @ K^T  for this warp's 16 rows  (8 n-tiles of 8 keys)
            float S[8][4] = {};
            #pragma unroll
            for (int ds = 0; ds < 8; ds++) {
                unsigned aq[4];
                aq[0] = Qs[(r0 + g) * QST + ds * 8 + t];
                aq[1] = Qs[(r0 + g + 8) * QST + ds * 8 + t];
                aq[2] = Qs[(r0 + g) * QST + ds * 8 + t + 4];
                aq[3] = Qs[(r0 + g + 8) * QST + ds * 8 + t + 4];
                #pragma unroll
                for (int ni = 0; ni < 8; ni++) {
                    unsigned bk[2];
                    bk[0] = Ks[(ds * 8 + t) * KST + ni * 8 + g];
                    bk[1] = Ks[(ds * 8 + t + 4) * KST + ni * 8 + g];
                    mma16n8k8(S[ni], aq, bk);
                }
            }

            // scale + causal mask
            const int rg0 = q0 + r0 + g, rg1 = rg0 + 8;
            const bool straddle = (k0 + 63 > q0 + r0);  // tile may need masking
            #pragma unroll
            for (int ni = 0; ni < 8; ni++) {
                int c0 = k0 + ni * 8 + 2 * t;
                S[ni][0] *= scale; S[ni][1] *= scale;
                S[ni][2] *= scale; S[ni][3] *= scale;
                if (straddle) {
                    if (c0 > rg0)     S[ni][0] = -1e30f;
                    if (c0 + 1 > rg0) S[ni][1] = -1e30f;
                    if (c0 > rg1)     S[ni][2] = -1e30f;
                    if (c0 + 1 > rg1) S[ni][3] = -1e30f;
                }
            }

            // online softmax (rows g and g+8; 4 lanes per row share g)
            float mx0 = -1e30f, mx1 = -1e30f;
            #pragma unroll
            for (int ni = 0; ni < 8; ni++) {
                mx0 = fmaxf(mx0, fmaxf(S[ni][0], S[ni][1]));
                mx1 = fmaxf(mx1, fmaxf(S[ni][2], S[ni][3]));
            }
            mx0 = fmaxf(mx0, __shfl_xor_sync(0xffffffffu, mx0, 1));
            mx0 = fmaxf(mx0, __shfl_xor_sync(0xffffffffu, mx0, 2));
            mx1 = fmaxf(mx1, __shfl_xor_sync(0xffffffffu, mx1, 1));
            mx1 = fmaxf(mx1, __shfl_xor_sync(0xffffffffu, mx1, 2));

            float mn0 = fmaxf(mrow[0], mx0), mn1 = fmaxf(mrow[1], mx1);
            float a0 = __expf(mrow[0] - mn0), a1 = __expf(mrow[1] - mn1);
            mrow[0] = mn0; mrow[1] = mn1;

            float s0 = 0.f, s1 = 0.f;
            #pragma unroll
            for (int ni = 0; ni < 8; ni++) {
                S[ni][0] = __expf(S[ni][0] - mn0);
                S[ni][1] = __expf(S[ni][1] - mn0);
                S[ni][2] = __expf(S[ni][2] - mn1);
                S[ni][3] = __expf(S[ni][3] - mn1);
                s0 += S[ni][0] + S[ni][1];
                s1 += S[ni][2] + S[ni][3];
            }
            s0 += __shfl_xor_sync(0xffffffffu, s0, 1);
            s0 += __shfl_xor_sync(0xffffffffu, s0, 2);
            s1 += __shfl_xor_sync(0xffffffffu, s1, 1);
            s1 += __shfl_xor_sync(0xffffffffu, s1, 2);
            lrow[0] = lrow[0] * a0 + s0;
            lrow[1] = lrow[1] * a1 + s1;

            #pragma unroll
            for (int di = 0; di < 8; di++) {
                O[di][0] *= a0; O[di][1] *= a0;
                O[di][2] *= a1; O[di][3] *= a1;
            }

            // stage P (warp-private rows) in A-frag-friendly layout
            #pragma unroll
            for (int ni = 0; ni < 8; ni++) {
                int c = ni * 8 + 2 * t;
                Ps[(r0 + g) * QST + c]     = f2tf(S[ni][0]);
                Ps[(r0 + g) * QST + c + 1] = f2tf(S[ni][1]);
                Ps[(r0 + g + 8) * QST + c]     = f2tf(S[ni][2]);
                Ps[(r0 + g + 8) * QST + c + 1] = f2tf(S[ni][3]);
            }
            __syncwarp();

            // O += P @ V
            #pragma unroll
            for (int cs = 0; cs < 8; cs++) {
                unsigned ap[4];
                ap[0] = Ps[(r0 + g) * QST + cs * 8 + t];
                ap[1] = Ps[(r0 + g + 8) * QST + cs * 8 + t];
                ap[2] = Ps[(r0 + g) * QST + cs * 8 + t + 4];
                ap[3] = Ps[(r0 + g + 8) * QST + cs * 8 + t + 4];
                #pragma unroll
                for (int di = 0; di < 8; di++) {
                    unsigned bv[2];
                    bv[0] = Vs[(cs * 8 + t) * KST + di * 8 + g];
                    bv[1] = Vs[(cs * 8 + t + 4) * KST + di * 8 + g];
                    mma16n8k8(O[di], ap, bv);
                }
            }
        }
    }

    // epilogue: normalize, write y[b][t][h*64+d]
    float inv0 = 1.f / lrow[0], inv1 = 1.f / lrow[1];
    int rg0 = q0 + r0 + g, rg1 = rg0 + 8;
    #pragma unroll
    for (int di = 0; di < 8; di++) {
        int c = h * DDIM + di * 8 + 2 * t;
        *(float2*)(y + ((size_t)b * TDIM + rg0) * CDIM + c) =
            make_float2(O[di][0] * inv0, O[di][1] * inv0);
        *(float2*)(y + ((size_t)b * TDIM + rg1) * CDIM + c) =
            make_float2(O[di][2] * inv1, O[di][3] * inv1);
    }
}

// ---------------------------------------------------------------------------
extern "C" void kernel_launch(void* const* d_in, const int* in_sizes, int n_in,
                              void* d_out, int out_size)
{
    const float* x     = (const float*)d_in[0];
    const float* Wqkv  = (const float*)d_in[1];
    const float* bqkv  = (const float*)d_in[2];
    const float* Wproj = (const float*)d_in[3];
    const float* bproj = (const float*)d_in[4];
    float* out = (float*)d_out;

    float* qkv; cudaGetSymbolAddress((void**)&qkv, g_qkv);
    float* yb;  cudaGetSymbolAddress((void**)&yb, g_y);

    // 1) QKV projection: [8192,768] @ [768,2304] + b
    gemm_tf32<<<dim3(C3 / 128, MROWS / 128), 256>>>(x, Wqkv, bqkv, qkv, MROWS, C3, CDIM);

    // 2) Causal flash attention
    size_t smem = (size_t)(128 * QST + 2 * 64 * KST + 128 * QST) * sizeof(unsigned); // 106496 B
    static int smem_set = 0;
    if (!smem_set) {
        cudaFuncSetAttribute(flash_tf32, cudaFuncAttributeMaxDynamicSharedMemorySize, (int)smem);
        smem_set = 1;
    }
    flash_tf32<<<dim3(TDIM / 128, HDIM, BDIM), 256, smem>>>(qkv, yb);

    // 3) Output projection: [8192,768] @ [768,768] + b
    gemm_tf32<<<dim3(CDIM / 128, MROWS / 128), 256>>>(yb, Wproj, bproj, out, MROWS, CDIM, CDIM);
}

// round 4
// speedup vs baseline: 2.7641x; 1.0790x over previous
#include <cuda_runtime.h>
#include <cuda_bf16.h>
#include <cstdint>

#define BDIM 4
#define TDIM 2048
#define CDIM 768
#define HDIM 12
#define DDIM 64
#define C3   2304
#define MROWS (BDIM * TDIM)

__device__ float g_qkv[MROWS * C3];
__device__ float g_y[MROWS * CDIM];

// ---------------------------------------------------------------------------
__device__ __forceinline__ unsigned f2tf(float x) {
    unsigned u;
    asm("cvt.rna.tf32.f32 %0, %1;" : "=r"(u) : "f"(x));
    return u;
}
__device__ __forceinline__ void mma16n8k8(float d[4], const unsigned a[4], const unsigned b[2]) {
    asm volatile(
        "mma.sync.aligned.m16n8k8.row.col.f32.tf32.tf32.f32 "
        "{%0,%1,%2,%3}, {%4,%5,%6,%7}, {%8,%9}, {%0,%1,%2,%3};\n"
        : "+f"(d[0]), "+f"(d[1]), "+f"(d[2]), "+f"(d[3])
        : "r"(a[0]), "r"(a[1]), "r"(a[2]), "r"(a[3]), "r"(b[0]), "r"(b[1]));
}
__device__ __forceinline__ void cp16(uint32_t dst, const float* src) {
    asm volatile("cp.async.cg.shared.global [%0], [%1], 16;" :: "r"(dst), "l"(src));
}
__device__ __forceinline__ void cp_commit() { asm volatile("cp.async.commit_group;"); }
__device__ __forceinline__ void cp_wait1() { asm volatile("cp.async.wait_group 1;"); }
__device__ __forceinline__ void cp_wait0() { asm volatile("cp.async.wait_group 0;"); }

// ---------------------------------------------------------------------------
// tf32 GEMM, cp.async double-buffered.  Block 128x128, BK=16, 256 thr,
// 8 warps of 64x32.  As[m][k] stride 20, Bs[k][n] stride 136 (raw fp32;
// cvt.rna at fragment load).
// ---------------------------------------------------------------------------
__global__ __launch_bounds__(256, 2)
void gemm_tf32(const float* __restrict__ A, const float* __restrict__ W,
               const float* __restrict__ bias, float* __restrict__ out,
               int M, int N, int K)
{
    __shared__ float As[2][128 * 20];
    __shared__ float Bs[2][16 * 136];

    const int tid  = threadIdx.x;
    const int lane = tid & 31, wid = tid >> 5;
    const int g = lane >> 2, t = lane & 3;
    const int wm = (wid & 1) * 64;
    const int wn = (wid >> 1) * 32;
    const int m0 = blockIdx.y * 128, n0 = blockIdx.x * 128;

    // staging assignments
    const int am = tid >> 1, ak = (tid & 1) * 8;
    const int bk = tid >> 4, bn8 = (tid & 15) * 8;

    const float* Ap = A + (size_t)(m0 + am) * K + ak;
    const float* Wp = W + (size_t)bk * N + n0 + bn8;

    uint32_t sA[2], sB[2];
    sA[0] = (uint32_t)__cvta_generic_to_shared(&As[0][am * 20 + ak]);
    sA[1] = (uint32_t)__cvta_generic_to_shared(&As[1][am * 20 + ak]);
    sB[0] = (uint32_t)__cvta_generic_to_shared(&Bs[0][bk * 136 + bn8]);
    sB[1] = (uint32_t)__cvta_generic_to_shared(&Bs[1][bk * 136 + bn8]);

    float acc[4][4][4] = {};

    // prologue: stage k0=0 into buf 0
    cp16(sA[0],      Ap);
    cp16(sA[0] + 16, Ap + 4);
    cp16(sB[0],      Wp);
    cp16(sB[0] + 16, Wp + 4);
    cp_commit();

    const int NK = K / 16;
    int buf = 0;
    for (int it = 0; it < NK; it++) {
        if (it + 1 < NK) {
            int nb = buf ^ 1;
            const float* ap = Ap + (it + 1) * 16;
            const float* wp = Wp + (size_t)(it + 1) * 16 * N;
            cp16(sA[nb],      ap);
            cp16(sA[nb] + 16, ap + 4);
            cp16(sB[nb],      wp);
            cp16(sB[nb] + 16, wp + 4);
            cp_commit();
            cp_wait1();
        } else {
            cp_wait0();
        }
        __syncthreads();

        const float* Ab = As[buf];
        const float* Bb = Bs[buf];
        #pragma unroll
        for (int kk = 0; kk < 16; kk += 8) {
            unsigned af[4][4], bf[4][2];
            #pragma unroll
            for (int mi = 0; mi < 4; mi++) {
                int r = wm + mi * 16;
                af[mi][0] = f2tf(Ab[(r + g) * 20 + kk + t]);
                af[mi][1] = f2tf(Ab[(r + g + 8) * 20 + kk + t]);
                af[mi][2] = f2tf(Ab[(r + g) * 20 + kk + t + 4]);
                af[mi][3] = f2tf(Ab[(r + g + 8) * 20 + kk + t + 4]);
            }
            #pragma unroll
            for (int ni = 0; ni < 4; ni++) {
                int c = wn + ni * 8 + g;
                bf[ni][0] = f2tf(Bb[(kk + t) * 136 + c]);
                bf[ni][1] = f2tf(Bb[(kk + t + 4) * 136 + c]);
            }
            #pragma unroll
            for (int mi = 0; mi < 4; mi++)
                #pragma unroll
                for (int ni = 0; ni < 4; ni++)
                    mma16n8k8(acc[mi][ni], af[mi], bf[ni]);
        }
        __syncthreads();
        buf ^= 1;
    }

    #pragma unroll
    for (int mi = 0; mi < 4; mi++) {
        #pragma unroll
        for (int ni = 0; ni < 4; ni++) {
            int r = m0 + wm + mi * 16 + g;
            int c = n0 + wn + ni * 8 + 2 * t;
            float b0 = bias[c], b1 = bias[c + 1];
            *(float2*)(out + (size_t)r * N + c) =
                make_float2(acc[mi][ni][0] + b0, acc[mi][ni][1] + b1);
            *(float2*)(out + (size_t)(r + 8) * N + c) =
                make_float2(acc[mi][ni][2] + b0, acc[mi][ni][3] + b1);
        }
    }
}

// ---------------------------------------------------------------------------
// Flash attention v3: cp.async double-buffered K/V, Q frags in registers,
// P through swizzled per-warp smem (LDS.128 reload).
// Kr: [64][68] raw fp32 (banks 4g+t on frag reads), Vr: [64][72] (banks 8t+g).
// ---------------------------------------------------------------------------
#define KR_W (64 * 68)
#define VR_W (64 * 72)
#define PS_OFF (2 * KR_W + 2 * VR_W)
#define FA_SMEM_W (PS_OFF + 8 * 1024)

extern __shared__ float fa_sm[];

__global__ __launch_bounds__(256, 2)
void flash_tf32(const float* __restrict__ qkv, float* __restrict__ y)
{
    const int tid  = threadIdx.x;
    const int lane = tid & 31, wid = tid >> 5;
    const int g = lane >> 2, t = lane & 3;
    const int r0 = wid * 16;
    const int itile = blockIdx.x, h = blockIdx.y, b = blockIdx.z;
    const int q0 = itile * 128;
    const size_t base = (size_t)b * TDIM * C3;
    const float scale = 0.125f;

    const uint32_t smem_base = (uint32_t)__cvta_generic_to_shared(fa_sm);

    // staging addresses: c = token-in-tile, dq = d quad
    const int sc = tid & 63, sdq = (tid >> 6) * 4;   // covers dq 0..12; +16 per step
    const float* kv_src = qkv + base + (size_t)sc * C3 + CDIM + h * DDIM + sdq;

    // ---- Q fragments from gmem (once) ----
    unsigned Qf[8][4];
    {
        const float* q0p = qkv + base + (size_t)(q0 + r0 + g) * C3 + h * DDIM;
        const float* q1p = q0p + 8 * C3;
        #pragma unroll
        for (int ds = 0; ds < 8; ds++) {
            Qf[ds][0] = f2tf(q0p[ds * 8 + t]);
            Qf[ds][1] = f2tf(q1p[ds * 8 + t]);
            Qf[ds][2] = f2tf(q0p[ds * 8 + t + 4]);
            Qf[ds][3] = f2tf(q1p[ds * 8 + t + 4]);
        }
    }

    float O[8][4] = {};
    float mrow[2] = {-1e30f, -1e30f};
    float lrow[2] = {0.f, 0.f};

    const int nkt = 2 * (itile + 1);

    // prologue: stage tile 0 into buf 0
    {
        const float* src = kv_src;   // k0 = 0
        #pragma unroll
        for (int i = 0; i < 4; i++) {
            uint32_t kd = smem_base + (uint32_t)(sc * 68 + sdq + i * 16) * 4;
            uint32_t vd = smem_base + (uint32_t)(2 * KR_W + sc * 72 + sdq + i * 16) * 4;
            cp16(kd, src + i * 16);
            cp16(vd, src + CDIM + i * 16);
        }
        cp_commit();
    }

    int buf = 0;
    for (int jt = 0; jt < nkt; jt++) {
        const int k0 = jt * 64;
        if (jt + 1 < nkt) {
            int nb = buf ^ 1;
            const float* src = kv_src + (size_t)(k0 + 64) * C3;
            #pragma unroll
            for (int i = 0; i < 4; i++) {
                uint32_t kd = smem_base + (uint32_t)(nb * KR_W + sc * 68 + sdq + i * 16) * 4;
                uint32_t vd = smem_base + (uint32_t)(2 * KR_W + nb * VR_W + sc * 72 + sdq + i * 16) * 4;
                cp16(kd, src + i * 16);
                cp16(vd, src + CDIM + i * 16);
            }
            cp_commit();
            cp_wait1();
        } else {
            cp_wait0();
        }
        __syncthreads();

        const float* Kr = fa_sm + buf * KR_W;
        const float* Vr = fa_sm + 2 * KR_W + buf * VR_W;
        float* Ps = fa_sm + PS_OFF + wid * 1024;

        const bool active = (k0 <= q0 + r0 + 15);
        if (active) {
            // S = Q @ K^T
            float S[8][4] = {};
            #pragma unroll
            for (int ds = 0; ds < 8; ds++) {
                #pragma unroll
                for (int ni = 0; ni < 8; ni++) {
                    unsigned bk[2];
                    bk[0] = f2tf(Kr[(ni * 8 + g) * 68 + ds * 8 + t]);
                    bk[1] = f2tf(Kr[(ni * 8 + g) * 68 + ds * 8 + t + 4]);
                    mma16n8k8(S[ni], Qf[ds], bk);
                }
            }

            // scale + causal mask
            const int rg0 = q0 + r0 + g, rg1 = rg0 + 8;
            const bool straddle = (k0 + 63 > q0 + r0);
            #pragma unroll
            for (int ni = 0; ni < 8; ni++) {
                int c0 = k0 + ni * 8 + 2 * t;
                S[ni][0] *= scale; S[ni][1] *= scale;
                S[ni][2] *= scale; S[ni][3] *= scale;
                if (straddle) {
                    if (c0 > rg0)     S[ni][0] = -1e30f;
                    if (c0 + 1 > rg0) S[ni][1] = -1e30f;
                    if (c0 > rg1)     S[ni][2] = -1e30f;
                    if (c0 + 1 > rg1) S[ni][3] = -1e30f;
                }
            }

            // online softmax
            float mx0 = -1e30f, mx1 = -1e30f;
            #pragma unroll
            for (int ni = 0; ni < 8; ni++) {
                mx0 = fmaxf(mx0, fmaxf(S[ni][0], S[ni][1]));
                mx1 = fmaxf(mx1, fmaxf(S[ni][2], S[ni][3]));
            }
            mx0 = fmaxf(mx0, __shfl_xor_sync(0xffffffffu, mx0, 1));
            mx0 = fmaxf(mx0, __shfl_xor_sync(0xffffffffu, mx0, 2));
            mx1 = fmaxf(mx1, __shfl_xor_sync(0xffffffffu, mx1, 1));
            mx1 = fmaxf(mx1, __shfl_xor_sync(0xffffffffu, mx1, 2));

            float mn0 = fmaxf(mrow[0], mx0), mn1 = fmaxf(mrow[1], mx1);
            float a0 = __expf(mrow[0] - mn0), a1 = __expf(mrow[1] - mn1);
            mrow[0] = mn0; mrow[1] = mn1;

            float s0 = 0.f, s1 = 0.f;
            #pragma unroll
            for (int ni = 0; ni < 8; ni++) {
                S[ni][0] = __expf(S[ni][0] - mn0);
                S[ni][1] = __expf(S[ni][1] - mn0);
                S[ni][2] = __expf(S[ni][2] - mn1);
                S[ni][3] = __expf(S[ni][3] - mn1);
                s0 += S[ni][0] + S[ni][1];
                s1 += S[ni][2] + S[ni][3];
            }
            s0 += __shfl_xor_sync(0xffffffffu, s0, 1);
            s0 += __shfl_xor_sync(0xffffffffu, s0, 2);
            s1 += __shfl_xor_sync(0xffffffffu, s1, 1);
            s1 += __shfl_xor_sync(0xffffffffu, s1, 2);
            lrow[0] = lrow[0] * a0 + s0;
            lrow[1] = lrow[1] * a1 + s1;

            #pragma unroll
            for (int di = 0; di < 8; di++) {
                O[di][0] *= a0; O[di][1] *= a0;
                O[di][2] *= a1; O[di][3] *= a1;
            }

            // P -> per-warp A-frag smem (swizzled), tf32
            {
                const int c0c = 2 * t, c1c = 2 * t + 1;
                const int tt0 = c0c & 3, h0 = (c0c >> 2) & 1;
                const int tt1 = c1c & 3;      // h1 == h0
                const int sw = g >> 1;
                unsigned* P32 = (unsigned*)Ps;
                #pragma unroll
                for (int ni = 0; ni < 8; ni++) {
                    unsigned* p0 = &P32[(ni * 32 + g * 4 + (tt0 ^ sw)) * 4 + 2 * h0];
                    unsigned* p1 = &P32[(ni * 32 + g * 4 + (tt1 ^ sw)) * 4 + 2 * h0];
                    p0[0] = f2tf(S[ni][0]);
                    p1[0] = f2tf(S[ni][1]);
                    p0[1] = f2tf(S[ni][2]);
                    p1[1] = f2tf(S[ni][3]);
                }
            }
            __syncwarp();

            // O += P @ V
            #pragma unroll
            for (int cs = 0; cs < 8; cs++) {
                const unsigned* P32 = (const unsigned*)Ps;
                uint4 ap4 = *(const uint4*)&P32[(cs * 32 + g * 4 + (t ^ (g >> 1))) * 4];
                unsigned ap[4] = {ap4.x, ap4.y, ap4.z, ap4.w};
                #pragma unroll
                for (int di = 0; di < 8; di++) {
                    unsigned bv[2];
                    bv[0] = f2tf(Vr[(cs * 8 + t) * 72 + di * 8 + g]);
                    bv[1] = f2tf(Vr[(cs * 8 + t + 4) * 72 + di * 8 + g]);
                    mma16n8k8(O[di], ap, bv);
                }
            }
        }
        __syncthreads();
        buf ^= 1;
    }

    // epilogue
    float inv0 = 1.f / lrow[0], inv1 = 1.f / lrow[1];
    int rg0 = q0 + r0 + g, rg1 = rg0 + 8;
    #pragma unroll
    for (int di = 0; di < 8; di++) {
        int c = h * DDIM + di * 8 + 2 * t;
        *(float2*)(y + ((size_t)b * TDIM + rg0) * CDIM + c) =
            make_float2(O[di][0] * inv0, O[di][1] * inv0);
        *(float2*)(y + ((size_t)b * TDIM + rg1) * CDIM + c) =
            make_float2(O[di][2] * inv1, O[di][3] * inv1);
    }
}

// ---------------------------------------------------------------------------
extern "C" void kernel_launch(void* const* d_in, const int* in_sizes, int n_in,
                              void* d_out, int out_size)
{
    const float* x     = (const float*)d_in[0];
    const float* Wqkv  = (const float*)d_in[1];
    const float* bqkv  = (const float*)d_in[2];
    const float* Wproj = (const float*)d_in[3];
    const float* bproj = (const float*)d_in[4];
    float* out = (float*)d_out;

    float* qkv; cudaGetSymbolAddress((void**)&qkv, g_qkv);
    float* yb;  cudaGetSymbolAddress((void**)&yb, g_y);

    gemm_tf32<<<dim3(C3 / 128, MROWS / 128), 256>>>(x, Wqkv, bqkv, qkv, MROWS, C3, CDIM);

    size_t smem = (size_t)FA_SMEM_W * sizeof(float);   // 104448 B
    cudaFuncSetAttribute(flash_tf32, cudaFuncAttributeMaxDynamicSharedMemorySize, (int)smem);
    flash_tf32<<<dim3(TDIM / 128, HDIM, BDIM), 256, smem>>>(qkv, yb);

    gemm_tf32<<<dim3(CDIM / 128, MROWS / 128), 256>>>(yb, Wproj, bproj, out, MROWS, CDIM, CDIM);
}

// round 6
// speedup vs baseline: 3.6485x; 1.3200x over previous
#include <cuda_runtime.h>
#include <cuda_bf16.h>
#include <cstdint>

#define BDIM 4
#define TDIM 2048
#define CDIM 768
#define HDIM 12
#define DDIM 64
#define C3   2304
#define MROWS (BDIM * TDIM)

__device__ float g_qkv[MROWS * C3];
__device__ float g_y[MROWS * CDIM];

// ---------------------------------------------------------------------------
// helpers
// ---------------------------------------------------------------------------
__device__ __forceinline__ unsigned f2h2(float lo, float hi) {
    unsigned r;
    asm("cvt.rn.f16x2.f32 %0, %1, %2;" : "=r"(r) : "f"(hi), "f"(lo));
    return r;
}
__device__ __forceinline__ void mma16816(float d[4], const unsigned a[4], const unsigned b[2]) {
    asm volatile(
        "mma.sync.aligned.m16n8k16.row.col.f32.f16.f16.f32 "
        "{%0,%1,%2,%3}, {%4,%5,%6,%7}, {%8,%9}, {%0,%1,%2,%3};\n"
        : "+f"(d[0]), "+f"(d[1]), "+f"(d[2]), "+f"(d[3])
        : "r"(a[0]), "r"(a[1]), "r"(a[2]), "r"(a[3]), "r"(b[0]), "r"(b[1]));
}
__device__ __forceinline__ void cp16(uint32_t dst, const float* src) {
    asm volatile("cp.async.cg.shared.global [%0], [%1], 16;" :: "r"(dst), "l"(src));
}
__device__ __forceinline__ void cp_commit() { asm volatile("cp.async.commit_group;"); }
__device__ __forceinline__ void cp_wait1() { asm volatile("cp.async.wait_group 1;"); }
__device__ __forceinline__ void cp_wait0() { asm volatile("cp.async.wait_group 0;"); }

// ---------------------------------------------------------------------------
// fp16 GEMM: out[M,N] = A[M,K] @ W[K,N] + bias.  Block 128x128, BK=16,
// 256 thr, 8 warps of 64x32.  cp.async fp32 staging; cvt at frag load.
// As stride 24 (LDS.64 conflict-free per 16-lane phase), Bs stride 132.
// ---------------------------------------------------------------------------
__global__ __launch_bounds__(256, 2)
void gemm_f16(const float* __restrict__ A, const float* __restrict__ W,
              const float* __restrict__ bias, float* __restrict__ out,
              int M, int N, int K)
{
    __shared__ float As[2][128 * 24];
    __shared__ float Bs[2][16 * 132];

    const int tid  = threadIdx.x;
    const int lane = tid & 31, wid = tid >> 5;
    const int g = lane >> 2, t = lane & 3;
    const int wm = (wid & 1) * 64;
    const int wn = (wid >> 1) * 32;
    const int m0 = blockIdx.y * 128, n0 = blockIdx.x * 128;

    const int am = tid >> 1, ak = (tid & 1) * 8;
    const int bk = tid >> 4, bn8 = (tid & 15) * 8;

    const float* Ap = A + (size_t)(m0 + am) * K + ak;
    const float* Wp = W + (size_t)bk * N + n0 + bn8;

    uint32_t sA[2], sB[2];
    sA[0] = (uint32_t)__cvta_generic_to_shared(&As[0][am * 24 + ak]);
    sA[1] = (uint32_t)__cvta_generic_to_shared(&As[1][am * 24 + ak]);
    sB[0] = (uint32_t)__cvta_generic_to_shared(&Bs[0][bk * 132 + bn8]);
    sB[1] = (uint32_t)__cvta_generic_to_shared(&Bs[1][bk * 132 + bn8]);

    float acc[4][4][4] = {};

    cp16(sA[0],      Ap);
    cp16(sA[0] + 16, Ap + 4);
    cp16(sB[0],      Wp);
    cp16(sB[0] + 16, Wp + 4);
    cp_commit();

    const int NK = K / 16;
    int buf = 0;
    for (int it = 0; it < NK; it++) {
        if (it + 1 < NK) {
            int nb = buf ^ 1;
            const float* ap = Ap + (it + 1) * 16;
            const float* wp = Wp + (size_t)(it + 1) * 16 * N;
            cp16(sA[nb],      ap);
            cp16(sA[nb] + 16, ap + 4);
            cp16(sB[nb],      wp);
            cp16(sB[nb] + 16, wp + 4);
            cp_commit();
            cp_wait1();
        } else {
            cp_wait0();
        }
        __syncthreads();

        const float* Ab = As[buf];
        const float* Bb = Bs[buf];

        unsigned af[4][4], bf[4][2];
        #pragma unroll
        for (int mi = 0; mi < 4; mi++) {
            int r = wm + mi * 16 + g;
            float2 a0 = *(const float2*)&Ab[r * 24 + 2 * t];
            float2 a1 = *(const float2*)&Ab[(r + 8) * 24 + 2 * t];
            float2 a2 = *(const float2*)&Ab[r * 24 + 2 * t + 8];
            float2 a3 = *(const float2*)&Ab[(r + 8) * 24 + 2 * t + 8];
            af[mi][0] = f2h2(a0.x, a0.y);
            af[mi][1] = f2h2(a1.x, a1.y);
            af[mi][2] = f2h2(a2.x, a2.y);
            af[mi][3] = f2h2(a3.x, a3.y);
        }
        #pragma unroll
        for (int ni = 0; ni < 4; ni++) {
            int c = wn + ni * 8 + g;
            bf[ni][0] = f2h2(Bb[(2 * t) * 132 + c],     Bb[(2 * t + 1) * 132 + c]);
            bf[ni][1] = f2h2(Bb[(2 * t + 8) * 132 + c], Bb[(2 * t + 9) * 132 + c]);
        }
        #pragma unroll
        for (int mi = 0; mi < 4; mi++)
            #pragma unroll
            for (int ni = 0; ni < 4; ni++)
                mma16816(acc[mi][ni], af[mi], bf[ni]);

        __syncthreads();
        buf ^= 1;
    }

    #pragma unroll
    for (int mi = 0; mi < 4; mi++) {
        #pragma unroll
        for (int ni = 0; ni < 4; ni++) {
            int r = m0 + wm + mi * 16 + g;
            int c = n0 + wn + ni * 8 + 2 * t;
            float b0 = bias[c], b1 = bias[c + 1];
            *(float2*)(out + (size_t)r * N + c) =
                make_float2(acc[mi][ni][0] + b0, acc[mi][ni][1] + b1);
            *(float2*)(out + (size_t)(r + 8) * N + c) =
                make_float2(acc[mi][ni][2] + b0, acc[mi][ni][3] + b1);
        }
    }
}

// ---------------------------------------------------------------------------
// Flash attention fp16: cp.async double-buffered K/V (raw fp32), Q frags in
// registers (scale folded), P fragments pure-register (fp16 C-frag == A-frag
// layout), no P smem.  Kr stride 72, Vr stride 76.
// ---------------------------------------------------------------------------
#define KR_W (64 * 72)
#define VR_W (64 * 76)
#define FA_SMEM_W (2 * KR_W + 2 * VR_W)

extern __shared__ float fa_sm[];

__global__ __launch_bounds__(256, 2)
void flash_f16(const float* __restrict__ qkv, float* __restrict__ y)
{
    const int tid  = threadIdx.x;
    const int lane = tid & 31, wid = tid >> 5;
    const int g = lane >> 2, t = lane & 3;
    const int r0 = wid * 16;
    const int itile = blockIdx.x, h = blockIdx.y, b = blockIdx.z;
    const int q0 = itile * 128;
    const size_t base = (size_t)b * TDIM * C3;

    const uint32_t smem_base = (uint32_t)__cvta_generic_to_shared(fa_sm);

    const int sc = tid & 63, sdq = (tid >> 6) * 4;
    const float* kv_src = qkv + base + (size_t)sc * C3 + CDIM + h * DDIM + sdq;

    // Q fragments (scale 1/8 folded in)
    unsigned Qf[4][4];
    {
        const float sc8 = 0.125f;
        const float* q0p = qkv + base + (size_t)(q0 + r0 + g) * C3 + h * DDIM;
        const float* q1p = q0p + 8 * C3;
        #pragma unroll
        for (int ds = 0; ds < 4; ds++) {
            float2 v0  = *(const float2*)&q0p[ds * 16 + 2 * t];
            float2 v0b = *(const float2*)&q0p[ds * 16 + 2 * t + 8];
            float2 v1  = *(const float2*)&q1p[ds * 16 + 2 * t];
            float2 v1b = *(const float2*)&q1p[ds * 16 + 2 * t + 8];
            Qf[ds][0] = f2h2(v0.x * sc8,  v0.y * sc8);
            Qf[ds][1] = f2h2(v1.x * sc8,  v1.y * sc8);
            Qf[ds][2] = f2h2(v0b.x * sc8, v0b.y * sc8);
            Qf[ds][3] = f2h2(v1b.x * sc8, v1b.y * sc8);
        }
    }

    float O[8][4] = {};
    float mrow[2] = {-1e30f, -1e30f};
    float lrow[2] = {0.f, 0.f};

    const int nkt = 2 * (itile + 1);

    // prologue: stage tile 0 into buf 0
    {
        const float* src = kv_src;
        #pragma unroll
        for (int i = 0; i < 4; i++) {
            uint32_t kd = smem_base + (uint32_t)(sc * 72 + sdq + i * 16) * 4;
            uint32_t vd = smem_base + (uint32_t)(2 * KR_W + sc * 76 + sdq + i * 16) * 4;
            cp16(kd, src + i * 16);
            cp16(vd, src + CDIM + i * 16);
        }
        cp_commit();
    }

    int buf = 0;
    for (int jt = 0; jt < nkt; jt++) {
        const int k0 = jt * 64;
        if (jt + 1 < nkt) {
            int nb = buf ^ 1;
            const float* src = kv_src + (size_t)(k0 + 64) * C3;
            #pragma unroll
            for (int i = 0; i < 4; i++) {
                uint32_t kd = smem_base + (uint32_t)(nb * KR_W + sc * 72 + sdq + i * 16) * 4;
                uint32_t vd = smem_base + (uint32_t)(2 * KR_W + nb * VR_W + sc * 76 + sdq + i * 16) * 4;
                cp16(kd, src + i * 16);
                cp16(vd, src + CDIM + i * 16);
            }
            cp_commit();
            cp_wait1();
        } else {
            cp_wait0();
        }
        __syncthreads();

        const float* Kr = fa_sm + buf * KR_W;
        const float* Vr = fa_sm + 2 * KR_W + buf * VR_W;

        const bool active = (k0 <= q0 + r0 + 15);
        if (active) {
            // S = (Q/8) @ K^T
            float S[8][4] = {};
            #pragma unroll
            for (int ds = 0; ds < 4; ds++) {
                #pragma unroll
                for (int ni = 0; ni < 8; ni++) {
                    const float* kp = &Kr[(ni * 8 + g) * 72 + ds * 16 + 2 * t];
                    float2 k0v = *(const float2*)kp;
                    float2 k1v = *(const float2*)(kp + 8);
                    unsigned bk[2];
                    bk[0] = f2h2(k0v.x, k0v.y);
                    bk[1] = f2h2(k1v.x, k1v.y);
                    mma16816(S[ni], Qf[ds], bk);
                }
            }

            // causal mask (diagonal-straddling tiles only; scale already folded)
            const int rg0 = q0 + r0 + g, rg1 = rg0 + 8;
            if (k0 + 63 > q0 + r0) {
                #pragma unroll
                for (int ni = 0; ni < 8; ni++) {
                    int c0 = k0 + ni * 8 + 2 * t;
                    if (c0 > rg0)     S[ni][0] = -1e30f;
                    if (c0 + 1 > rg0) S[ni][1] = -1e30f;
                    if (c0 > rg1)     S[ni][2] = -1e30f;
                    if (c0 + 1 > rg1) S[ni][3] = -1e30f;
                }
            }

            // online softmax
            float mx0 = -1e30f, mx1 = -1e30f;
            #pragma unroll
            for (int ni = 0; ni < 8; ni++) {
                mx0 = fmaxf(mx0, fmaxf(S[ni][0], S[ni][1]));
                mx1 = fmaxf(mx1, fmaxf(S[ni][2], S[ni][3]));
            }
            mx0 = fmaxf(mx0, __shfl_xor_sync(0xffffffffu, mx0, 1));
            mx0 = fmaxf(mx0, __shfl_xor_sync(0xffffffffu, mx0, 2));
            mx1 = fmaxf(mx1, __shfl_xor_sync(0xffffffffu, mx1, 1));
            mx1 = fmaxf(mx1, __shfl_xor_sync(0xffffffffu, mx1, 2));

            float mn0 = fmaxf(mrow[0], mx0), mn1 = fmaxf(mrow[1], mx1);
            float a0 = __expf(mrow[0] - mn0), a1 = __expf(mrow[1] - mn1);
            mrow[0] = mn0; mrow[1] = mn1;

            float s0 = 0.f, s1 = 0.f;
            #pragma unroll
            for (int ni = 0; ni < 8; ni++) {
                S[ni][0] = __expf(S[ni][0] - mn0);
                S[ni][1] = __expf(S[ni][1] - mn0);
                S[ni][2] = __expf(S[ni][2] - mn1);
                S[ni][3] = __expf(S[ni][3] - mn1);
                s0 += S[ni][0] + S[ni][1];
                s1 += S[ni][2] + S[ni][3];
            }
            s0 += __shfl_xor_sync(0xffffffffu, s0, 1);
            s0 += __shfl_xor_sync(0xffffffffu, s0, 2);
            s1 += __shfl_xor_sync(0xffffffffu, s1, 1);
            s1 += __shfl_xor_sync(0xffffffffu, s1, 2);
            lrow[0] = lrow[0] * a0 + s0;
            lrow[1] = lrow[1] * a1 + s1;

            #pragma unroll
            for (int di = 0; di < 8; di++) {
                O[di][0] *= a0; O[di][1] *= a0;
                O[di][2] *= a1; O[di][3] *= a1;
            }

            // O += P @ V  — P A-frags are register cvts of S C-frags
            #pragma unroll
            for (int cs = 0; cs < 4; cs++) {
                unsigned ap[4];
                ap[0] = f2h2(S[2 * cs][0],     S[2 * cs][1]);
                ap[1] = f2h2(S[2 * cs][2],     S[2 * cs][3]);
                ap[2] = f2h2(S[2 * cs + 1][0], S[2 * cs + 1][1]);
                ap[3] = f2h2(S[2 * cs + 1][2], S[2 * cs + 1][3]);
                #pragma unroll
                for (int di = 0; di < 8; di++) {
                    const float* vp = &Vr[(cs * 16 + 2 * t) * 76 + di * 8 + g];
                    unsigned bv[2];
                    bv[0] = f2h2(vp[0],        vp[76]);
                    bv[1] = f2h2(vp[8 * 76],   vp[9 * 76]);
                    mma16816(O[di], ap, bv);
                }
            }
        }
        __syncthreads();
        buf ^= 1;
    }

    // epilogue: normalize, write
    float inv0 = 1.f / lrow[0], inv1 = 1.f / lrow[1];
    int rg0 = q0 + r0 + g, rg1 = rg0 + 8;
    #pragma unroll
    for (int di = 0; di < 8; di++) {
        int c = h * DDIM + di * 8 + 2 * t;
        *(float2*)(y + ((size_t)b * TDIM + rg0) * CDIM + c) =
            make_float2(O[di][0] * inv0, O[di][1] * inv0);
        *(float2*)(y + ((size_t)b * TDIM + rg1) * CDIM + c) =
            make_float2(O[di][2] * inv1, O[di][3] * inv1);
    }
}

// ---------------------------------------------------------------------------
extern "C" void kernel_launch(void* const* d_in, const int* in_sizes, int n_in,
                              void* d_out, int out_size)
{
    const float* x     = (const float*)d_in[0];
    const float* Wqkv  = (const float*)d_in[1];
    const float* bqkv  = (const float*)d_in[2];
    const float* Wproj = (const float*)d_in[3];
    const float* bproj = (const float*)d_in[4];
    float* out = (float*)d_out;

    float* qkv; cudaGetSymbolAddress((void**)&qkv, g_qkv);
    float* yb;  cudaGetSymbolAddress((void**)&yb, g_y);

    gemm_f16<<<dim3(C3 / 128, MROWS / 128), 256>>>(x, Wqkv, bqkv, qkv, MROWS, C3, CDIM);

    size_t smem = (size_t)FA_SMEM_W * sizeof(float);   // 75776 B
    cudaFuncSetAttribute(flash_f16, cudaFuncAttributeMaxDynamicSharedMemorySize, (int)smem);
    flash_f16<<<dim3(TDIM / 128, HDIM, BDIM), 256, smem>>>(qkv, yb);

    gemm_f16<<<dim3(CDIM / 128, MROWS / 128), 256>>>(yb, Wproj, bproj, out, MROWS, CDIM, CDIM);
}

// round 7
// speedup vs baseline: 4.8300x; 1.3238x over previous
#include <cuda_runtime.h>
#include <cuda_fp16.h>
#include <cstdint>

#define BDIM 4
#define TDIM 2048
#define CDIM 768
#define HDIM 12
#define DDIM 64
#define C3   2304
#define MROWS (BDIM * TDIM)

__device__ __half g_qkv[MROWS * C3];   // fp16; Q section pre-scaled by 0.125
__device__ float  g_y[MROWS * CDIM];

// ---------------------------------------------------------------------------
// helpers
// ---------------------------------------------------------------------------
__device__ __forceinline__ unsigned f2h2(float lo, float hi) {
    unsigned r;
    asm("cvt.rn.f16x2.f32 %0, %1, %2;" : "=r"(r) : "f"(hi), "f"(lo));
    return r;
}
__device__ __forceinline__ void mma16816(float d[4], const unsigned a[4], const unsigned b[2]) {
    asm volatile(
        "mma.sync.aligned.m16n8k16.row.col.f32.f16.f16.f32 "
        "{%0,%1,%2,%3}, {%4,%5,%6,%7}, {%8,%9}, {%0,%1,%2,%3};\n"
        : "+f"(d[0]), "+f"(d[1]), "+f"(d[2]), "+f"(d[3])
        : "r"(a[0]), "r"(a[1]), "r"(a[2]), "r"(a[3]), "r"(b[0]), "r"(b[1]));
}
__device__ __forceinline__ void cp16(uint32_t dst, const void* src) {
    asm volatile("cp.async.cg.shared.global [%0], [%1], 16;" :: "r"(dst), "l"(src));
}
__device__ __forceinline__ void cp_commit() { asm volatile("cp.async.commit_group;"); }
__device__ __forceinline__ void cp_wait1() { asm volatile("cp.async.wait_group 1;"); }
__device__ __forceinline__ void cp_wait0() { asm volatile("cp.async.wait_group 0;"); }

__device__ __forceinline__ void ldsm4(unsigned& r0, unsigned& r1, unsigned& r2, unsigned& r3,
                                      uint32_t addr) {
    asm volatile("ldmatrix.sync.aligned.m8n8.x4.shared.b16 {%0,%1,%2,%3}, [%4];"
                 : "=r"(r0), "=r"(r1), "=r"(r2), "=r"(r3) : "r"(addr));
}
__device__ __forceinline__ void ldsm4t(unsigned& r0, unsigned& r1, unsigned& r2, unsigned& r3,
                                       uint32_t addr) {
    asm volatile("ldmatrix.sync.aligned.m8n8.x4.trans.shared.b16 {%0,%1,%2,%3}, [%4];"
                 : "=r"(r0), "=r"(r1), "=r"(r2), "=r"(r3) : "r"(addr));
}

// ---------------------------------------------------------------------------
// fp16 GEMM, 3-stage cp.async, 1 sync/iter.  Block 128x128, BK=16, 256 thr,
// 8 warps of 64x32.  fp32 staging; cvt at frag load.
// As stride 24, Bs stride 132 (conflict-free frag reads).
// OutT: __half (QSCALE: cols<768 scaled 0.125) or float.
// ---------------------------------------------------------------------------
#define GA_SZ (128 * 24)
#define GB_SZ (16 * 132)
#define GS_BYTES ((3 * GA_SZ + 3 * GB_SZ) * 4)

template<typename OutT, int QSCALE>
__global__ __launch_bounds__(256, 2)
void gemm_f16(const float* __restrict__ A, const float* __restrict__ W,
              const float* __restrict__ bias, OutT* __restrict__ out,
              int M, int N, int K)
{
    extern __shared__ float gsm[];

    const int tid  = threadIdx.x;
    const int lane = tid & 31, wid = tid >> 5;
    const int g = lane >> 2, t = lane & 3;
    const int wm = (wid & 1) * 64;
    const int wn = (wid >> 1) * 32;
    const int m0 = blockIdx.y * 128, n0 = blockIdx.x * 128;

    const int am = tid >> 1, ak = (tid & 1) * 8;
    const int bk = tid >> 4, bn8 = (tid & 15) * 8;

    const float* Ap = A + (size_t)(m0 + am) * K + ak;
    const float* Wp = W + (size_t)bk * N + n0 + bn8;

    const uint32_t sbase = (uint32_t)__cvta_generic_to_shared(gsm);
    uint32_t sA[3], sB[3];
    #pragma unroll
    for (int i = 0; i < 3; i++) {
        sA[i] = sbase + (uint32_t)(i * GA_SZ + am * 24 + ak) * 4;
        sB[i] = sbase + (uint32_t)(3 * GA_SZ + i * GB_SZ + bk * 132 + bn8) * 4;
    }

    float acc[4][4][4] = {};

    const int NK = K / 16;
    // prologue: stage iters 0,1
    #pragma unroll
    for (int p = 0; p < 2; p++) {
        const float* ap = Ap + p * 16;
        const float* wp = Wp + (size_t)p * 16 * N;
        cp16(sA[p],      ap);
        cp16(sA[p] + 16, ap + 4);
        cp16(sB[p],      wp);
        cp16(sB[p] + 16, wp + 4);
        cp_commit();
    }

    for (int it = 0; it < NK; it++) {
        if (it < NK - 1) cp_wait1(); else cp_wait0();
        __syncthreads();

        if (it + 2 < NK) {
            int nb = (it + 2) % 3;
            const float* ap = Ap + (it + 2) * 16;
            const float* wp = Wp + (size_t)(it + 2) * 16 * N;
            cp16(sA[nb],      ap);
            cp16(sA[nb] + 16, ap + 4);
            cp16(sB[nb],      wp);
            cp16(sB[nb] + 16, wp + 4);
            cp_commit();
        }

        const int buf = it % 3;
        const float* Ab = gsm + buf * GA_SZ;
        const float* Bb = gsm + 3 * GA_SZ + buf * GB_SZ;

        unsigned af[4][4], bf[4][2];
        #pragma unroll
        for (int mi = 0; mi < 4; mi++) {
            int r = wm + mi * 16 + g;
            float2 a0 = *(const float2*)&Ab[r * 24 + 2 * t];
            float2 a1 = *(const float2*)&Ab[(r + 8) * 24 + 2 * t];
            float2 a2 = *(const float2*)&Ab[r * 24 + 2 * t + 8];
            float2 a3 = *(const float2*)&Ab[(r + 8) * 24 + 2 * t + 8];
            af[mi][0] = f2h2(a0.x, a0.y);
            af[mi][1] = f2h2(a1.x, a1.y);
            af[mi][2] = f2h2(a2.x, a2.y);
            af[mi][3] = f2h2(a3.x, a3.y);
        }
        #pragma unroll
        for (int ni = 0; ni < 4; ni++) {
            int c = wn + ni * 8 + g;
            bf[ni][0] = f2h2(Bb[(2 * t) * 132 + c],     Bb[(2 * t + 1) * 132 + c]);
            bf[ni][1] = f2h2(Bb[(2 * t + 8) * 132 + c], Bb[(2 * t + 9) * 132 + c]);
        }
        #pragma unroll
        for (int mi = 0; mi < 4; mi++)
            #pragma unroll
            for (int ni = 0; ni < 4; ni++)
                mma16816(acc[mi][ni], af[mi], bf[ni]);
    }

    #pragma unroll
    for (int mi = 0; mi < 4; mi++) {
        #pragma unroll
        for (int ni = 0; ni < 4; ni++) {
            int r = m0 + wm + mi * 16 + g;
            int c = n0 + wn + ni * 8 + 2 * t;
            float b0 = bias[c], b1 = bias[c + 1];
            float v0 = acc[mi][ni][0] + b0, v1 = acc[mi][ni][1] + b1;
            float v2 = acc[mi][ni][2] + b0, v3 = acc[mi][ni][3] + b1;
            if (QSCALE && c < CDIM) {
                v0 *= 0.125f; v1 *= 0.125f; v2 *= 0.125f; v3 *= 0.125f;
            }
            if constexpr (sizeof(OutT) == 2) {
                __half* o = (__half*)out;
                *(__half2*)(o + (size_t)r * N + c) =
                    __floats2half2_rn(v0, v1);
                *(__half2*)(o + (size_t)(r + 8) * N + c) =
                    __floats2half2_rn(v2, v3);
            } else {
                float* o = (float*)out;
                *(float2*)(o + (size_t)r * N + c) = make_float2(v0, v1);
                *(float2*)(o + (size_t)(r + 8) * N + c) = make_float2(v2, v3);
            }
        }
    }
}

// ---------------------------------------------------------------------------
// Flash attention fp16: triple-buffered cp.async K/V (fp16, XOR-swizzled
// 128B rows), ldmatrix fragment feeds, Q frags from gmem, P in registers.
// smem: K[3][64][64]h, V[3][64][64]h = 49152 B.
// ---------------------------------------------------------------------------
#define FTILE 8192            // bytes per K or V tile buffer

extern __shared__ __align__(16) char fa_smc[];

__global__ __launch_bounds__(256, 2)
void flash_f16(const __half* __restrict__ qh, float* __restrict__ y)
{
    const int tid  = threadIdx.x;
    const int lane = tid & 31, wid = tid >> 5;
    const int g = lane >> 2, t = lane & 3;
    const int r0 = wid * 16;
    const int itile = blockIdx.x, h = blockIdx.y, b = blockIdx.z;
    const int q0 = itile * 128;
    const size_t base = (size_t)b * TDIM * C3;

    const uint32_t sbase = (uint32_t)__cvta_generic_to_shared(fa_smc);

    // staging: row c = tid>>2, segs {2*(tid&3), +1}; 16B chunks
    const int sc = tid >> 2, ss0 = (tid & 3) * 2;
    const __half* kv_src = qh + base + (size_t)sc * C3 + CDIM + h * DDIM;

    // Q fragments straight from gmem (Q pre-scaled by 0.125 in GEMM epilogue)
    unsigned Qf[4][4];
    {
        const __half* q0p = qh + base + (size_t)(q0 + r0 + g) * C3 + h * DDIM;
        const __half* q1p = q0p + 8 * C3;
        #pragma unroll
        for (int ds = 0; ds < 4; ds++) {
            Qf[ds][0] = *(const unsigned*)(q0p + ds * 16 + 2 * t);
            Qf[ds][1] = *(const unsigned*)(q1p + ds * 16 + 2 * t);
            Qf[ds][2] = *(const unsigned*)(q0p + ds * 16 + 2 * t + 8);
            Qf[ds][3] = *(const unsigned*)(q1p + ds * 16 + 2 * t + 8);
        }
    }

    float O[8][4] = {};
    float mrow[2] = {-1e30f, -1e30f};
    float lrow[2] = {0.f, 0.f};

    const int nkt = 2 * (itile + 1);

    // stage tile jt into buffer jt%3 (own commit group)
    auto stage = [&](int jt) {
        const int bi = jt % 3;
        const __half* src = kv_src + (size_t)(jt * 64) * C3;
        const uint32_t krow = sbase + (uint32_t)bi * FTILE + sc * 128;
        const uint32_t vrow = krow + 3 * FTILE;
        #pragma unroll
        for (int si = 0; si < 2; si++) {
            int s = ss0 + si;
            uint32_t off = (uint32_t)((s ^ (sc & 7)) << 4);
            cp16(krow + off, src + s * 8);
            cp16(vrow + off, src + CDIM + s * 8);
        }
        cp_commit();
    };

    stage(0);
    stage(1);

    for (int jt = 0; jt < nkt; jt++) {
        const int k0 = jt * 64;
        if (jt < nkt - 1) cp_wait1(); else cp_wait0();
        __syncthreads();
        if (jt + 2 < nkt) stage(jt + 2);

        const int bi = jt % 3;
        const uint32_t kb = sbase + (uint32_t)bi * FTILE;
        const uint32_t vb = kb + 3 * FTILE;

        const bool active = (k0 <= q0 + r0 + 15);
        if (active) {
            // S = Q @ K^T : B-frags via ldmatrix.x4 (K rows are col-major B)
            float S[8][4] = {};
            #pragma unroll
            for (int ni = 0; ni < 8; ni++) {
                unsigned bk[4][2];
                #pragma unroll
                for (int p = 0; p < 2; p++) {
                    int c  = ni * 8 + (lane & 7);
                    int sg = 4 * p + (lane >> 3);
                    uint32_t addr = kb + (uint32_t)(c * 128 + ((sg ^ (c & 7)) << 4));
                    ldsm4(bk[2 * p][0], bk[2 * p][1], bk[2 * p + 1][0], bk[2 * p + 1][1], addr);
                }
                #pragma unroll
                for (int ds = 0; ds < 4; ds++)
                    mma16816(S[ni], Qf[ds], bk[ds]);
            }

            // causal mask (diagonal-straddling tiles only)
            const int rg0 = q0 + r0 + g, rg1 = rg0 + 8;
            if (k0 + 63 > q0 + r0) {
                #pragma unroll
                for (int ni = 0; ni < 8; ni++) {
                    int c0 = k0 + ni * 8 + 2 * t;
                    if (c0 > rg0)     S[ni][0] = -1e30f;
                    if (c0 + 1 > rg0) S[ni][1] = -1e30f;
                    if (c0 > rg1)     S[ni][2] = -1e30f;
                    if (c0 + 1 > rg1) S[ni][3] = -1e30f;
                }
            }

            // online softmax
            float mx0 = -1e30f, mx1 = -1e30f;
            #pragma unroll
            for (int ni = 0; ni < 8; ni++) {
                mx0 = fmaxf(mx0, fmaxf(S[ni][0], S[ni][1]));
                mx1 = fmaxf(mx1, fmaxf(S[ni][2], S[ni][3]));
            }
            mx0 = fmaxf(mx0, __shfl_xor_sync(0xffffffffu, mx0, 1));
            mx0 = fmaxf(mx0, __shfl_xor_sync(0xffffffffu, mx0, 2));
            mx1 = fmaxf(mx1, __shfl_xor_sync(0xffffffffu, mx1, 1));
            mx1 = fmaxf(mx1, __shfl_xor_sync(0xffffffffu, mx1, 2));

            float mn0 = fmaxf(mrow[0], mx0), mn1 = fmaxf(mrow[1], mx1);
            float a0 = __expf(mrow[0] - mn0), a1 = __expf(mrow[1] - mn1);
            mrow[0] = mn0; mrow[1] = mn1;

            float s0 = 0.f, s1 = 0.f;
            #pragma unroll
            for (int ni = 0; ni < 8; ni++) {
                S[ni][0] = __expf(S[ni][0] - mn0);
                S[ni][1] = __expf(S[ni][1] - mn0);
                S[ni][2] = __expf(S[ni][2] - mn1);
                S[ni][3] = __expf(S[ni][3] - mn1);
                s0 += S[ni][0] + S[ni][1];
                s1 += S[ni][2] + S[ni][3];
            }
            s0 += __shfl_xor_sync(0xffffffffu, s0, 1);
            s0 += __shfl_xor_sync(0xffffffffu, s0, 2);
            s1 += __shfl_xor_sync(0xffffffffu, s1, 1);
            s1 += __shfl_xor_sync(0xffffffffu, s1, 2);
            lrow[0] = lrow[0] * a0 + s0;
            lrow[1] = lrow[1] * a1 + s1;

            #pragma unroll
            for (int di = 0; di < 8; di++) {
                O[di][0] *= a0; O[di][1] *= a0;
                O[di][2] *= a1; O[di][3] *= a1;
            }

            // O += P @ V : P a-frags via register cvt; V b-frags via ldmatrix.trans
            #pragma unroll
            for (int cs = 0; cs < 4; cs++) {
                unsigned ap[4];
                ap[0] = f2h2(S[2 * cs][0],     S[2 * cs][1]);
                ap[1] = f2h2(S[2 * cs][2],     S[2 * cs][3]);
                ap[2] = f2h2(S[2 * cs + 1][0], S[2 * cs + 1][1]);
                ap[3] = f2h2(S[2 * cs + 1][2], S[2 * cs + 1][3]);
                #pragma unroll
                for (int dp = 0; dp < 4; dp++) {
                    int row = cs * 16 + ((lane >> 3) & 1) * 8 + (lane & 7);
                    int sg  = 2 * dp + (lane >> 4);
                    uint32_t addr = vb + (uint32_t)(row * 128 + ((sg ^ (row & 7)) << 4));
                    unsigned bv[4];
                    ldsm4t(bv[0], bv[1], bv[2], bv[3], addr);
                    mma16816(O[2 * dp],     ap, bv);
                    mma16816(O[2 * dp + 1], ap, bv + 2);
                }
            }
        }
    }

    // epilogue: normalize, write fp32 y
    float inv0 = 1.f / lrow[0], inv1 = 1.f / lrow[1];
    int rg0 = q0 + r0 + g, rg1 = rg0 + 8;
    #pragma unroll
    for (int di = 0; di < 8; di++) {
        int c = h * DDIM + di * 8 + 2 * t;
        *(float2*)(y + ((size_t)b * TDIM + rg0) * CDIM + c) =
            make_float2(O[di][0] * inv0, O[di][1] * inv0);
        *(float2*)(y + ((size_t)b * TDIM + rg1) * CDIM + c) =
            make_float2(O[di][2] * inv1, O[di][3] * inv1);
    }
}

// ---------------------------------------------------------------------------
extern "C" void kernel_launch(void* const* d_in, const int* in_sizes, int n_in,
                              void* d_out, int out_size)
{
    const float* x     = (const float*)d_in[0];
    const float* Wqkv  = (const float*)d_in[1];
    const float* bqkv  = (const float*)d_in[2];
    const float* Wproj = (const float*)d_in[3];
    const float* bproj = (const float*)d_in[4];
    float* out = (float*)d_out;

    __half* qkv; cudaGetSymbolAddress((void**)&qkv, g_qkv);
    float*  yb;  cudaGetSymbolAddress((void**)&yb, g_y);

    cudaFuncSetAttribute(gemm_f16<__half, 1>, cudaFuncAttributeMaxDynamicSharedMemorySize, GS_BYTES);
    cudaFuncSetAttribute(gemm_f16<float, 0>,  cudaFuncAttributeMaxDynamicSharedMemorySize, GS_BYTES);

    // 1) QKV projection -> fp16 (Q cols scaled by 0.125)
    gemm_f16<__half, 1><<<dim3(C3 / 128, MROWS / 128), 256, GS_BYTES>>>(
        x, Wqkv, bqkv, qkv, MROWS, C3, CDIM);

    // 2) Causal flash attention (fp16 inputs, fp32 out)
    size_t fsm = 6 * FTILE;   // 49152 B
    cudaFuncSetAttribute(flash_f16, cudaFuncAttributeMaxDynamicSharedMemorySize, (int)fsm);
    flash_f16<<<dim3(TDIM / 128, HDIM, BDIM), 256, fsm>>>(qkv, yb);

    // 3) Output projection -> fp32
    gemm_f16<float, 0><<<dim3(CDIM / 128, MROWS / 128), 256, GS_BYTES>>>(
        yb, Wproj, bproj, out, MROWS, CDIM, CDIM);
}

// round 10
// speedup vs baseline: 6.7266x; 1.3927x over previous
#include <cuda_runtime.h>
#include <cuda_fp16.h>
#include <cstdint>

#define BDIM 4
#define TDIM 2048
#define CDIM 768
#define HDIM 12
#define DDIM 64
#define C3   2304
#define MROWS (BDIM * TDIM)

// fp16 scratch
__device__ __half g_xh[MROWS * CDIM];     // x in fp16
__device__ __half g_wqkv[CDIM * C3];      // W_qkv fp16
__device__ __half g_wproj[CDIM * CDIM];   // W_proj fp16
__device__ __half g_qkv[MROWS * C3];      // qkv (Q pre-scaled by 0.125)
__device__ __half g_y[MROWS * CDIM];      // attention output fp16

// ---------------------------------------------------------------------------
// helpers
// ---------------------------------------------------------------------------
__device__ __forceinline__ unsigned f2h2(float lo, float hi) {
    unsigned r;
    asm("cvt.rn.f16x2.f32 %0, %1, %2;" : "=r"(r) : "f"(hi), "f"(lo));
    return r;
}
__device__ __forceinline__ void mma16816(float d[4], const unsigned a[4], const unsigned b[2]) {
    asm volatile(
        "mma.sync.aligned.m16n8k16.row.col.f32.f16.f16.f32 "
        "{%0,%1,%2,%3}, {%4,%5,%6,%7}, {%8,%9}, {%0,%1,%2,%3};\n"
        : "+f"(d[0]), "+f"(d[1]), "+f"(d[2]), "+f"(d[3])
        : "r"(a[0]), "r"(a[1]), "r"(a[2]), "r"(a[3]), "r"(b[0]), "r"(b[1]));
}
__device__ __forceinline__ void cp16(uint32_t dst, const void* src) {
    asm volatile("cp.async.cg.shared.global [%0], [%1], 16;" :: "r"(dst), "l"(src));
}
__device__ __forceinline__ void cp_commit() { asm volatile("cp.async.commit_group;"); }
__device__ __forceinline__ void cp_wait1() { asm volatile("cp.async.wait_group 1;"); }
__device__ __forceinline__ void cp_wait0() { asm volatile("cp.async.wait_group 0;"); }

__device__ __forceinline__ void ldsm4(unsigned& r0, unsigned& r1, unsigned& r2, unsigned& r3,
                                      uint32_t addr) {
    asm volatile("ldmatrix.sync.aligned.m8n8.x4.shared.b16 {%0,%1,%2,%3}, [%4];"
                 : "=r"(r0), "=r"(r1), "=r"(r2), "=r"(r3) : "r"(addr));
}
__device__ __forceinline__ void ldsm4t(unsigned& r0, unsigned& r1, unsigned& r2, unsigned& r3,
                                       uint32_t addr) {
    asm volatile("ldmatrix.sync.aligned.m8n8.x4.trans.shared.b16 {%0,%1,%2,%3}, [%4];"
                 : "=r"(r0), "=r"(r1), "=r"(r2), "=r"(r3) : "r"(addr));
}

// ---------------------------------------------------------------------------
// fp32 -> fp16 convert
// ---------------------------------------------------------------------------
__global__ void f2h_kernel(const float* __restrict__ in, __half* __restrict__ out, int n)
{
    int i = (blockIdx.x * blockDim.x + threadIdx.x) * 4;
    if (i < n) {
        float4 v = *(const float4*)(in + i);
        __half2* o = (__half2*)(out + i);
        o[0] = __floats2half2_rn(v.x, v.y);
        o[1] = __floats2half2_rn(v.z, v.w);
    }
}

// ---------------------------------------------------------------------------
// fp16 GEMM: out[M,N] = A[M,K] @ W[K,N] + bias.  Block 128x128, BK=64,
// 256 thr, 8 warps of 64x32, 3-stage cp.async, ldmatrix operand feeds.
// smem/stage: A 128x64h (128B rows, XOR-swizzled) + B 64x128h (256B rows).
// ---------------------------------------------------------------------------
#define GSTAGE 32768
#define GS_BYTES (3 * GSTAGE)

template<typename OutT, int QSCALE>
__global__ __launch_bounds__(256, 2)
void gemm_h(const __half* __restrict__ A, const __half* __restrict__ W,
            const float* __restrict__ bias, OutT* __restrict__ out,
            int M, int N, int K)
{
    extern __shared__ __align__(16) char gsmc[];
    const uint32_t sbase = (uint32_t)__cvta_generic_to_shared(gsmc);

    const int tid  = threadIdx.x;
    const int lane = tid & 31, wid = tid >> 5;
    const int g = lane >> 2, t = lane & 3;
    const int wm = (wid & 1) * 64;
    const int wn = (wid >> 1) * 32;
    const int m0 = blockIdx.y * 128, n0 = blockIdx.x * 128;

    // staging: A row ar (128B = 8 segs), 2 threads/row; B row br (256B = 16 segs), 4 threads/row
    const int ar = tid >> 1, as0 = (tid & 1) * 4;
    const int br = tid >> 2, bs0 = (tid & 3) * 4;
    const __half* Ap = A + (size_t)(m0 + ar) * K + as0 * 8;
    const __half* Wp = W + (size_t)br * N + n0 + bs0 * 8;

    auto stageg = [&](int it) {
        const uint32_t ab = sbase + (uint32_t)(it % 3) * GSTAGE;
        const uint32_t bb = ab + 16384;
        const __half* ap = Ap + it * 64;
        const __half* wp = Wp + (size_t)it * 64 * N;
        #pragma unroll
        for (int s = 0; s < 4; s++) {
            int seg = as0 + s;
            cp16(ab + (uint32_t)(ar * 128 + ((seg ^ (ar & 7)) << 4)), ap + s * 8);
        }
        #pragma unroll
        for (int s = 0; s < 4; s++) {
            int seg = bs0 + s;
            cp16(bb + (uint32_t)(br * 256 + ((seg ^ (br & 7)) << 4)), wp + s * 8);
        }
        cp_commit();
    };

    float acc[4][4][4] = {};

    const int NK = K / 64;
    stageg(0);
    stageg(1);

    for (int it = 0; it < NK; it++) {
        if (it < NK - 1) cp_wait1(); else cp_wait0();
        __syncthreads();
        if (it + 2 < NK) stageg(it + 2);

        const uint32_t ab = sbase + (uint32_t)(it % 3) * GSTAGE;
        const uint32_t bb = ab + 16384;

        #pragma unroll
        for (int kc = 0; kc < 4; kc++) {
            unsigned af[4][4];
            #pragma unroll
            for (int mi = 0; mi < 4; mi++) {
                int row = wm + mi * 16 + (lane & 15);
                int sg  = kc * 2 + (lane >> 4);
                ldsm4(af[mi][0], af[mi][1], af[mi][2], af[mi][3],
                      ab + (uint32_t)(row * 128 + ((sg ^ (row & 7)) << 4)));
            }
            unsigned bf[4][2];
            #pragma unroll
            for (int np = 0; np < 2; np++) {
                int row = kc * 16 + ((lane >> 3) & 1) * 8 + (lane & 7);
                int sg  = (wn >> 3) + 2 * np + (lane >> 4);
                unsigned b0, b1, b2, b3;
                ldsm4t(b0, b1, b2, b3,
                       bb + (uint32_t)(row * 256 + ((sg ^ (row & 7)) << 4)));
                bf[2 * np][0] = b0; bf[2 * np][1] = b1;
                bf[2 * np + 1][0] = b2; bf[2 * np + 1][1] = b3;
            }
            #pragma unroll
            for (int mi = 0; mi < 4; mi++)
                #pragma unroll
                for (int ni = 0; ni < 4; ni++)
                    mma16816(acc[mi][ni], af[mi], bf[ni]);
        }
        __syncthreads();
    }

    #pragma unroll
    for (int mi = 0; mi < 4; mi++) {
        #pragma unroll
        for (int ni = 0; ni < 4; ni++) {
            int r = m0 + wm + mi * 16 + g;
            int c = n0 + wn + ni * 8 + 2 * t;
            float b0 = bias[c], b1 = bias[c + 1];
            float v0 = acc[mi][ni][0] + b0, v1 = acc[mi][ni][1] + b1;
            float v2 = acc[mi][ni][2] + b0, v3 = acc[mi][ni][3] + b1;
            if (QSCALE && c < CDIM) {
                v0 *= 0.125f; v1 *= 0.125f; v2 *= 0.125f; v3 *= 0.125f;
            }
            if constexpr (sizeof(OutT) == 2) {
                __half* o = (__half*)out;
                *(__half2*)(o + (size_t)r * N + c) = __floats2half2_rn(v0, v1);
                *(__half2*)(o + (size_t)(r + 8) * N + c) = __floats2half2_rn(v2, v3);
            } else {
                float* o = (float*)out;
                *(float2*)(o + (size_t)r * N + c) = make_float2(v0, v1);
                *(float2*)(o + (size_t)(r + 8) * N + c) = make_float2(v2, v3);
            }
        }
    }
}

// ---------------------------------------------------------------------------
// Flash attention fp16 (round-7 structure; output now fp16).
// ---------------------------------------------------------------------------
#define FTILE 8192

extern __shared__ __align__(16) char fa_smc[];

__global__ __launch_bounds__(256, 2)
void flash_f16(const __half* __restrict__ qh, __half* __restrict__ y)
{
    const int tid  = threadIdx.x;
    const int lane = tid & 31, wid = tid >> 5;
    const int g = lane >> 2, t = lane & 3;
    const int r0 = wid * 16;
    const int itile = blockIdx.x, h = blockIdx.y, b = blockIdx.z;
    const int q0 = itile * 128;
    const size_t base = (size_t)b * TDIM * C3;

    const uint32_t sbase = (uint32_t)__cvta_generic_to_shared(fa_smc);

    const int sc = tid >> 2, ss0 = (tid & 3) * 2;
    const __half* kv_src = qh + base + (size_t)sc * C3 + CDIM + h * DDIM;

    unsigned Qf[4][4];
    {
        const __half* q0p = qh + base + (size_t)(q0 + r0 + g) * C3 + h * DDIM;
        const __half* q1p = q0p + 8 * C3;
        #pragma unroll
        for (int ds = 0; ds < 4; ds++) {
            Qf[ds][0] = *(const unsigned*)(q0p + ds * 16 + 2 * t);
            Qf[ds][1] = *(const unsigned*)(q1p + ds * 16 + 2 * t);
            Qf[ds][2] = *(const unsigned*)(q0p + ds * 16 + 2 * t + 8);
            Qf[ds][3] = *(const unsigned*)(q1p + ds * 16 + 2 * t + 8);
        }
    }

    float O[8][4] = {};
    float mrow[2] = {-1e30f, -1e30f};
    float lrow[2] = {0.f, 0.f};

    const int nkt = 2 * (itile + 1);

    auto stage = [&](int jt) {
        const int bi = jt % 3;
        const __half* src = kv_src + (size_t)(jt * 64) * C3;
        const uint32_t krow = sbase + (uint32_t)bi * FTILE + sc * 128;
        const uint32_t vrow = krow + 3 * FTILE;
        #pragma unroll
        for (int si = 0; si < 2; si++) {
            int s = ss0 + si;
            uint32_t off = (uint32_t)((s ^ (sc & 7)) << 4);
            cp16(krow + off, src + s * 8);
            cp16(vrow + off, src + CDIM + s * 8);
        }
        cp_commit();
    };

    stage(0);
    stage(1);

    for (int jt = 0; jt < nkt; jt++) {
        const int k0 = jt * 64;
        if (jt < nkt - 1) cp_wait1(); else cp_wait0();
        __syncthreads();
        if (jt + 2 < nkt) stage(jt + 2);

        const int bi = jt % 3;
        const uint32_t kb = sbase + (uint32_t)bi * FTILE;
        const uint32_t vb = kb + 3 * FTILE;

        const bool active = (k0 <= q0 + r0 + 15);
        if (active) {
            float S[8][4] = {};
            #pragma unroll
            for (int ni = 0; ni < 8; ni++) {
                unsigned bk[4][2];
                #pragma unroll
                for (int p = 0; p < 2; p++) {
                    int c  = ni * 8 + (lane & 7);
                    int sg = 4 * p + (lane >> 3);
                    uint32_t addr = kb + (uint32_t)(c * 128 + ((sg ^ (c & 7)) << 4));
                    ldsm4(bk[2 * p][0], bk[2 * p][1], bk[2 * p + 1][0], bk[2 * p + 1][1], addr);
                }
                #pragma unroll
                for (int ds = 0; ds < 4; ds++)
                    mma16816(S[ni], Qf[ds], bk[ds]);
            }

            const int rg0 = q0 + r0 + g, rg1 = rg0 + 8;
            if (k0 + 63 > q0 + r0) {
                #pragma unroll
                for (int ni = 0; ni < 8; ni++) {
                    int c0 = k0 + ni * 8 + 2 * t;
                    if (c0 > rg0)     S[ni][0] = -1e30f;
                    if (c0 + 1 > rg0) S[ni][1] = -1e30f;
                    if (c0 > rg1)     S[ni][2] = -1e30f;
                    if (c0 + 1 > rg1) S[ni][3] = -1e30f;
                }
            }

            float mx0 = -1e30f, mx1 = -1e30f;
            #pragma unroll
            for (int ni = 0; ni < 8; ni++) {
                mx0 = fmaxf(mx0, fmaxf(S[ni][0], S[ni][1]));
                mx1 = fmaxf(mx1, fmaxf(S[ni][2], S[ni][3]));
            }
            mx0 = fmaxf(mx0, __shfl_xor_sync(0xffffffffu, mx0, 1));
            mx0 = fmaxf(mx0, __shfl_xor_sync(0xffffffffu, mx0, 2));
            mx1 = fmaxf(mx1, __shfl_xor_sync(0xffffffffu, mx1, 1));
            mx1 = fmaxf(mx1, __shfl_xor_sync(0xffffffffu, mx1, 2));

            float mn0 = fmaxf(mrow[0], mx0), mn1 = fmaxf(mrow[1], mx1);
            float a0 = __expf(mrow[0] - mn0), a1 = __expf(mrow[1] - mn1);
            mrow[0] = mn0; mrow[1] = mn1;

            float s0 = 0.f, s1 = 0.f;
            #pragma unroll
            for (int ni = 0; ni < 8; ni++) {
                S[ni][0] = __expf(S[ni][0] - mn0);
                S[ni][1] = __expf(S[ni][1] - mn0);
                S[ni][2] = __expf(S[ni][2] - mn1);
                S[ni][3] = __expf(S[ni][3] - mn1);
                s0 += S[ni][0] + S[ni][1];
                s1 += S[ni][2] + S[ni][3];
            }
            s0 += __shfl_xor_sync(0xffffffffu, s0, 1);
            s0 += __shfl_xor_sync(0xffffffffu, s0, 2);
            s1 += __shfl_xor_sync(0xffffffffu, s1, 1);
            s1 += __shfl_xor_sync(0xffffffffu, s1, 2);
            lrow[0] = lrow[0] * a0 + s0;
            lrow[1] = lrow[1] * a1 + s1;

            #pragma unroll
            for (int di = 0; di < 8; di++) {
                O[di][0] *= a0; O[di][1] *= a0;
                O[di][2] *= a1; O[di][3] *= a1;
            }

            #pragma unroll
            for (int cs = 0; cs < 4; cs++) {
                unsigned ap[4];
                ap[0] = f2h2(S[2 * cs][0],     S[2 * cs][1]);
                ap[1] = f2h2(S[2 * cs][2],     S[2 * cs][3]);
                ap[2] = f2h2(S[2 * cs + 1][0], S[2 * cs + 1][1]);
                ap[3] = f2h2(S[2 * cs + 1][2], S[2 * cs + 1][3]);
                #pragma unroll
                for (int dp = 0; dp < 4; dp++) {
                    int row = cs * 16 + ((lane >> 3) & 1) * 8 + (lane & 7);
                    int sg  = 2 * dp + (lane >> 4);
                    uint32_t addr = vb + (uint32_t)(row * 128 + ((sg ^ (row & 7)) << 4));
                    unsigned bv[4];
                    ldsm4t(bv[0], bv[1], bv[2], bv[3], addr);
                    mma16816(O[2 * dp],     ap, bv);
                    mma16816(O[2 * dp + 1], ap, bv + 2);
                }
            }
        }
    }

    // epilogue: normalize, write fp16 y
    float inv0 = 1.f / lrow[0], inv1 = 1.f / lrow[1];
    int rg0 = q0 + r0 + g, rg1 = rg0 + 8;
    #pragma unroll
    for (int di = 0; di < 8; di++) {
        int c = h * DDIM + di * 8 + 2 * t;
        *(__half2*)(y + ((size_t)b * TDIM + rg0) * CDIM + c) =
            __floats2half2_rn(O[di][0] * inv0, O[di][1] * inv0);
        *(__half2*)(y + ((size_t)b * TDIM + rg1) * CDIM + c) =
            __floats2half2_rn(O[di][2] * inv1, O[di][3] * inv1);
    }
}

// ---------------------------------------------------------------------------
extern "C" void kernel_launch(void* const* d_in, const int* in_sizes, int n_in,
                              void* d_out, int out_size)
{
    const float* x     = (const float*)d_in[0];
    const float* Wqkv  = (const float*)d_in[1];
    const float* bqkv  = (const float*)d_in[2];
    const float* Wproj = (const float*)d_in[3];
    const float* bproj = (const float*)d_in[4];
    float* out = (float*)d_out;

    __half *xh, *wqkv, *wproj, *qkv, *yb;
    cudaGetSymbolAddress((void**)&xh, g_xh);
    cudaGetSymbolAddress((void**)&wqkv, g_wqkv);
    cudaGetSymbolAddress((void**)&wproj, g_wproj);
    cudaGetSymbolAddress((void**)&qkv, g_qkv);
    cudaGetSymbolAddress((void**)&yb, g_y);

    // 0) fp32 -> fp16 conversions
    f2h_kernel<<<(MROWS * CDIM / 4 + 255) / 256, 256>>>(x, xh, MROWS * CDIM);
    f2h_kernel<<<(CDIM * C3 / 4 + 255) / 256, 256>>>(Wqkv, wqkv, CDIM * C3);
    f2h_kernel<<<(CDIM * CDIM / 4 + 255) / 256, 256>>>(Wproj, wproj, CDIM * CDIM);

    cudaFuncSetAttribute(gemm_h<__half, 1>, cudaFuncAttributeMaxDynamicSharedMemorySize, GS_BYTES);
    cudaFuncSetAttribute(gemm_h<float, 0>,  cudaFuncAttributeMaxDynamicSharedMemorySize, GS_BYTES);

    // 1) QKV projection -> fp16 (Q cols scaled by 0.125)
    gemm_h<__half, 1><<<dim3(C3 / 128, MROWS / 128), 256, GS_BYTES>>>(
        xh, wqkv, bqkv, qkv, MROWS, C3, CDIM);

    // 2) Causal flash attention (fp16 in/out)
    size_t fsm = 6 * FTILE;
    cudaFuncSetAttribute(flash_f16, cudaFuncAttributeMaxDynamicSharedMemorySize, (int)fsm);
    flash_f16<<<dim3(TDIM / 128, HDIM, BDIM), 256, fsm>>>(qkv, yb);

    // 3) Output projection -> fp32
    gemm_h<float, 0><<<dim3(CDIM / 128, MROWS / 128), 256, GS_BYTES>>>(
        yb, wproj, bproj, out, MROWS, CDIM, CDIM);
}